// round 13
// baseline (speedup 1.0000x reference)
#include <cuda_runtime.h>

#define LOG2E 1.4426950408889634f
#define LN2   0.6931471805599453f
#define CHUNK 64
#define MAXC  16         // ceil(1023/64)
#define NPK   9          // 0..3 = q-quads (backward), 4..7 = r-quads (forward), 8 = gather + partial chunk

__device__ float g_qv[1024][MAXC][64];
__device__ float g_rv[1024][MAXC - 1][64];
__device__ float g_qoff[1024][MAXC];
__device__ float g_roff[1024][MAXC - 1];
__device__ float g_seqs[1024];
__device__ float g_partial[1024];
__device__ unsigned int g_done[1024];   // zero-init; self-resetting
__device__ unsigned int g_count = 0;

static __device__ __forceinline__ float ex2f_(float x) {
    float y; asm("ex2.approx.ftz.f32 %0, %1;" : "=f"(y) : "f"(x)); return y;
}
static __device__ __forceinline__ float lg2f_(float x) {
    float y; asm("lg2.approx.ftz.f32 %0, %1;" : "=f"(y) : "f"(x)); return y;
}
static __device__ __forceinline__ unsigned long long pack2_(float lo, float hi) {
    unsigned long long d;
    asm("mov.b64 %0, {%1, %2};" : "=l"(d) : "f"(lo), "f"(hi));
    return d;
}
static __device__ __forceinline__ unsigned long long fma2_(unsigned long long a,
                                                           unsigned long long b,
                                                           unsigned long long c) {
    unsigned long long d;
    asm("fma.rn.f32x2 %0, %1, %2, %3;" : "=l"(d) : "l"(a), "l"(b), "l"(c));
    return d;
}
static __device__ __forceinline__ unsigned long long addx2_(unsigned long long a,
                                                            unsigned long long b) {
    unsigned long long d;
    asm("add.rn.f32x2 %0, %1, %2;" : "=l"(d) : "l"(a), "l"(b));
    return d;
}
static __device__ __forceinline__ void unpack2_(unsigned long long v, float& lo, float& hi) {
    asm("mov.b64 {%0, %1}, %2;" : "=f"(lo), "=f"(hi) : "l"(v));
}
static __device__ __forceinline__ float wredsum_(float v) {
#pragma unroll
    for (int m = 16; m > 0; m >>= 1) v += __shfl_xor_sync(0xffffffffu, v, m);
    return v;
}

// Half-contraction over this warp's 32-index half of BUF for states jO and jF.
#define MACHP(BUF, SO, SF)                                                  \
    {                                                                       \
        const ulonglong2* wv_ = (const ulonglong2*)(BUF);                   \
        unsigned long long o0_=0ull, o1_=0ull, f0_=0ull, f1_=0ull;          \
        _Pragma("unroll")                                                   \
        for (int k_ = 0; k_ < 8; k_++) {                                    \
            ulonglong2 q_ = wv_[k_];                                        \
            o0_ = fma2_(q_.x, eO[2*k_],     o0_);                           \
            o1_ = fma2_(q_.y, eO[2*k_ + 1], o1_);                           \
            f0_ = fma2_(q_.x, eF[2*k_],     f0_);                           \
            f1_ = fma2_(q_.y, eF[2*k_ + 1], f1_);                           \
        }                                                                   \
        float lo_, hi_;                                                     \
        unpack2_(addx2_(o0_, o1_), lo_, hi_); SO = lo_ + hi_;               \
        unpack2_(addx2_(f0_, f1_), lo_, hi_); SF = lo_ + hi_;               \
    }

// ---------------- backward per-chain pieces ----------------
#define BPH_(X, UU, PB)                                                     \
    {                                                                       \
        float p_;                                                           \
        if (PB) { float l_ = lg2f_(dsh##X[(PB)^1]); loff##X += l_;          \
                  p_ = ex2f_(fmaf(pf##X[UU], LOG2E, -l_)); }                \
        else p_ = ex2f_(pf##X[UU] * LOG2E);                                 \
        pf##X[UU] = *(const float*)(potc + off##X);                         \
        off##X = max(off##X - 256, offlo##X);                               \
        float y_ = x##X * p_;                                               \
        wsh##X[jO] = y_;                                                    \
        if (jO == 0) dsh##X[PB] = y_;                                       \
    }

#define BMAC_(X, PB)                                                        \
    { float sF_; MACHP(&wsh##X[h << 5], m##X##_, sF_) pp##X[PB][jF] = sF_; }

#define BQUAD(UU, PB)                                                       \
    {                                                                       \
        BPH_(A, UU, PB) BPH_(B, UU, PB) BPH_(C, UU, PB) BPH_(D, UU, PB)     \
        __syncwarp();                                                       \
        float mA_, mB_, mC_, mD_;                                           \
        BMAC_(A, PB) BMAC_(B, PB) BMAC_(C, PB) BMAC_(D, PB)                 \
        __syncthreads();                                                    \
        xA = mA_ + ppA[PB][jO]; xB = mB_ + ppB[PB][jO];                     \
        xC = mC_ + ppC[PB][jO]; xD = mD_ + ppD[PB][jO];                     \
    }

#define BSOLO(UU, PB)                                                       \
    {                                                                       \
        BPH_(A, UU, PB)                                                     \
        __syncwarp();                                                       \
        float mA_;                                                          \
        BMAC_(A, PB)                                                        \
        __syncthreads();                                                    \
        xA = mA_ + ppA[PB][jO];                                             \
    }

// ---------------- forward per-chain pieces ----------------
#define FPH_(X, UU, PB)                                                     \
    float p##X##_;                                                          \
    if (PB) { float l##X##_ = lg2f_(dsh##X[1]); loff##X += l##X##_;         \
              p##X##_ = ex2f_(fmaf(pf##X[UU], LOG2E, -l##X##_)); }          \
    else { p##X##_ = ex2f_(pf##X[UU] * LOG2E); }                            \
    pf##X[UU] = *(const float*)(potc + off##X);                             \
    off##X = min(off##X + 256, offhi##X);

#define FMC_(X, PB)                                                         \
    { float sF_; MACHP(&wsh##X[h << 5], m##X##_, sF_) pp##X[PB][jF] = sF_; }

#define FST_(X, PB)                                                         \
    {                                                                       \
        float v_ = (m##X##_ + pp##X[PB][jO]) * p##X##_;                     \
        wsh##X[jO] = v_;                                                    \
        if (jO == 0) dsh##X[PB] = v_;                                       \
    }

#define FQUAD(UU, PB)                                                       \
    {                                                                       \
        FPH_(A, UU, PB) FPH_(B, UU, PB) FPH_(C, UU, PB) FPH_(D, UU, PB)     \
        float mA_, mB_, mC_, mD_;                                           \
        FMC_(A, PB) FMC_(B, PB) FMC_(C, PB) FMC_(D, PB)                     \
        __syncthreads();                                                    \
        FST_(A, PB) FST_(B, PB) FST_(C, PB) FST_(D, PB)                     \
        __syncwarp();                                                       \
    }

// One CTA (64 threads, 2 warps) per (batch, quad). Warp h owns i-half [32h,32h+32),
// lane owns state jO = 32h + lane.
__global__ __launch_bounds__(64, 8) void crf_all_kernel(
    const float* __restrict__ pot,     // [B, T, 64]
    const int*   __restrict__ tags,    // [B, T]
    const int*   __restrict__ seqlen,  // [B]
    const float* __restrict__ K,       // [64, 64]
    const float* __restrict__ sw,      // [B]
    float*       __restrict__ out,
    int T, int B)
{
    const int b    = blockIdx.x / NPK;
    const int k    = blockIdx.x % NPK;
    const int tid  = threadIdx.x;
    const int lane = tid & 31;
    const int h    = tid >> 5;
    const int jO   = (h << 5) + lane;
    const int jF   = ((1 - h) << 5) + lane;

    int L = seqlen[b];
    if (L > T) L = T;
    if (L < 1) L = 1;
    const int M  = L - 1;
    const int nc = (M + CHUNK - 1) / CHUNK;

    const float* potb = pot + (size_t)b * T * 64;
    const char*  potc = (const char*)potb;
    const int s4 = jO << 2;

    __shared__ __align__(16) float wshA[64], wshB[64], wshC[64], wshD[64];
    __shared__ float ppA[2][64], ppB[2][64], ppC[2][64], ppD[2][64];
    __shared__ float dshA[2], dshB[2], dshC[2], dshD[2];
    __shared__ float sred[64];

    int cnt = 1;

    if (k == 8) {
        // ================= gathers + partial chunk (chunk nc) =================
        const int* tagb = tags + (size_t)b * T;
        float acc = 0.f;
        for (int t = tid; t < T; t += 64) {
            if (t < L) {
                int tg = tagb[t];
                acc += __ldg(potb + (size_t)t * 64 + tg);
                if (t >= 1) acc += __ldg(K + tagb[t - 1] * 64 + tg);
            }
        }
        sred[tid] = acc;
        __syncthreads();
        if (h == 0) {
            float v = sred[lane] + sred[lane + 32];
            v = wredsum_(v);
            if (lane == 0) g_seqs[b] = v;
        }

        if (nc >= 1) {
            // solo backward chain for the (possibly partial) last chunk
            const int a    = (nc - 1) * CHUNK + 1;
            const int bend = M;
            const int ns   = bend - a + 1;       // 1..64
            const int offloA = a * 256 + s4;

            unsigned long long eO[16], eF[16];
            const float4* krO = (const float4*)(K + jO * 64 + (h << 5));
            const float4* krF = (const float4*)(K + jF * 64 + (h << 5));
#pragma unroll
            for (int m = 0; m < 8; m++) {
                float4 vO = krO[m], vF = krF[m];
                eO[2*m]   = pack2_(ex2f_(vO.x * LOG2E), ex2f_(vO.y * LOG2E));
                eO[2*m+1] = pack2_(ex2f_(vO.z * LOG2E), ex2f_(vO.w * LOG2E));
                eF[2*m]   = pack2_(ex2f_(vF.x * LOG2E), ex2f_(vF.y * LOG2E));
                eF[2*m+1] = pack2_(ex2f_(vF.z * LOG2E), ex2f_(vF.w * LOG2E));
            }

            float loffA = 0.f, xA = 1.0f;
            float pfA[4];
#pragma unroll
            for (int u = 0; u < 4; u++) {
                int r = bend - u; if (r < a) r = a;
                pfA[u] = potb[(size_t)r * 64 + jO];
            }
            int offA = (bend - 4) * 256 + s4;
            if (offA < offloA) offA = offloA;
            if (tid == 0) { dshA[0] = dshA[1] = 1.0f; }
            __syncthreads();

            int n4 = ns >> 2;
#pragma unroll 1
            for (int it = 0; it < n4; it++) {
                BSOLO(0, 0) BSOLO(1, 1) BSOLO(2, 0) BSOLO(3, 1)
            }
            int rem = ns & 3;
            if (rem > 0) BSOLO(0, 0)
            if (rem > 1) BSOLO(1, 1)
            if (rem > 2) BSOLO(2, 0)

            g_qv[b][nc - 1][jO] = xA;
            if (tid == 0) g_qoff[b][nc - 1] = loffA;
            cnt = 2;
        }
    } else {
        // ================= quad task: 4 full 64-step chains =================
        const bool is_q  = (k < 4);
        const int  kp    = is_q ? k : (k - 4);
        const int  nfull = nc - 1;
        int nv = nfull - 4 * kp; if (nv > 4) nv = 4;
        if (nv <= 0) return;       // no arrival
        cnt = nv;

        const int cA = 4 * kp + 1;
        const int cB = (nv > 1) ? cA + 1 : cA;
        const int cC = (nv > 2) ? cA + 2 : cA;
        const int cD = (nv > 3) ? cA + 3 : cA;

        const int aA = (cA - 1) * CHUNK + 1, bendA = cA * CHUNK;
        const int aB = (cB - 1) * CHUNK + 1, bendB = cB * CHUNK;
        const int aC = (cC - 1) * CHUNK + 1, bendC = cC * CHUNK;
        const int aD = (cD - 1) * CHUNK + 1, bendD = cD * CHUNK;

        const int offloA = aA * 256 + s4, offhiA = bendA * 256 + s4;
        const int offloB = aB * 256 + s4, offhiB = bendB * 256 + s4;
        const int offloC = aC * 256 + s4, offhiC = bendC * 256 + s4;
        const int offloD = aD * 256 + s4, offhiD = bendD * 256 + s4;

        unsigned long long eO[16], eF[16];
        if (is_q) {
            const float4* krO = (const float4*)(K + jO * 64 + (h << 5));
            const float4* krF = (const float4*)(K + jF * 64 + (h << 5));
#pragma unroll
            for (int m = 0; m < 8; m++) {
                float4 vO = krO[m], vF = krF[m];
                eO[2*m]   = pack2_(ex2f_(vO.x * LOG2E), ex2f_(vO.y * LOG2E));
                eO[2*m+1] = pack2_(ex2f_(vO.z * LOG2E), ex2f_(vO.w * LOG2E));
                eF[2*m]   = pack2_(ex2f_(vF.x * LOG2E), ex2f_(vF.y * LOG2E));
                eF[2*m+1] = pack2_(ex2f_(vF.z * LOG2E), ex2f_(vF.w * LOG2E));
            }
        } else {
#pragma unroll
            for (int m = 0; m < 16; m++) {
                int r0 = (h << 5) + 2 * m;
                eO[m] = pack2_(ex2f_(K[r0 * 64 + jO]       * LOG2E),
                               ex2f_(K[(r0 + 1) * 64 + jO] * LOG2E));
                eF[m] = pack2_(ex2f_(K[r0 * 64 + jF]       * LOG2E),
                               ex2f_(K[(r0 + 1) * 64 + jF] * LOG2E));
            }
        }

        float loffA = 0.f, loffB = 0.f, loffC = 0.f, loffD = 0.f;
        float pfA[4], pfB[4], pfC[4], pfD[4];
        if (tid == 0) {
            dshA[0] = dshA[1] = 1.0f; dshB[0] = dshB[1] = 1.0f;
            dshC[0] = dshC[1] = 1.0f; dshD[0] = dshD[1] = 1.0f;
        }

        if (is_q) {
            float xA = 1.0f, xB = 1.0f, xC = 1.0f, xD = 1.0f;
#pragma unroll
            for (int u = 0; u < 4; u++) {
                pfA[u] = potb[(size_t)(bendA - u) * 64 + jO];
                pfB[u] = potb[(size_t)(bendB - u) * 64 + jO];
                pfC[u] = potb[(size_t)(bendC - u) * 64 + jO];
                pfD[u] = potb[(size_t)(bendD - u) * 64 + jO];
            }
            int offA = (bendA - 4) * 256 + s4;
            int offB = (bendB - 4) * 256 + s4;
            int offC = (bendC - 4) * 256 + s4;
            int offD = (bendD - 4) * 256 + s4;
            __syncthreads();

#pragma unroll 1
            for (int it = 0; it < 16; it++) {
                BQUAD(0, 0) BQUAD(1, 1) BQUAD(2, 0) BQUAD(3, 1)
            }

            g_qv[b][cA - 1][jO] = xA;
            if (tid == 0) g_qoff[b][cA - 1] = loffA;
            if (nv > 1) { g_qv[b][cB - 1][jO] = xB; if (tid == 0) g_qoff[b][cB - 1] = loffB; }
            if (nv > 2) { g_qv[b][cC - 1][jO] = xC; if (tid == 0) g_qoff[b][cC - 1] = loffC; }
            if (nv > 3) { g_qv[b][cD - 1][jO] = xD; if (tid == 0) g_qoff[b][cD - 1] = loffD; }
        } else {
            wshA[jO] = 1.0f; wshB[jO] = 1.0f; wshC[jO] = 1.0f; wshD[jO] = 1.0f;
#pragma unroll
            for (int u = 0; u < 4; u++) {
                pfA[u] = potb[(size_t)(aA + u) * 64 + jO];
                pfB[u] = potb[(size_t)(aB + u) * 64 + jO];
                pfC[u] = potb[(size_t)(aC + u) * 64 + jO];
                pfD[u] = potb[(size_t)(aD + u) * 64 + jO];
            }
            int offA = (aA + 4) * 256 + s4;
            int offB = (aB + 4) * 256 + s4;
            int offC = (aC + 4) * 256 + s4;
            int offD = (aD + 4) * 256 + s4;
            __syncthreads();

#pragma unroll 1
            for (int it = 0; it < 16; it++) {
                FQUAD(0, 0) FQUAD(1, 1) FQUAD(2, 0) FQUAD(3, 1)
            }

            g_rv[b][cA - 1][jO] = wshA[jO];
            if (tid == 0) g_roff[b][cA - 1] = loffA;
            if (nv > 1) { g_rv[b][cB - 1][jO] = wshB[jO]; if (tid == 0) g_roff[b][cB - 1] = loffB; }
            if (nv > 2) { g_rv[b][cC - 1][jO] = wshC[jO]; if (tid == 0) g_roff[b][cC - 1] = loffC; }
            if (nv > 3) { g_rv[b][cD - 1][jO] = wshD[jO]; if (tid == 0) g_roff[b][cD - 1] = loffD; }
        }
    }

    // ================= arrival + inline stitch (last task of batch) =================
    __threadfence();
    __syncthreads();
    if (h != 0) return;

    const unsigned int ntasks = (nc >= 1) ? (unsigned)(2 + 2 * (nc - 1)) : 1u;
    unsigned int old = 0;
    if (lane == 0) old = atomicAdd(&g_done[b], (unsigned)cnt);
    old = __shfl_sync(0xffffffffu, old, 0);
    if (old + (unsigned)cnt != ntasks) return;

    if (lane == 0) g_done[b] = 0;    // reset for graph replay
    __threadfence();

    float p0lo = ex2f_(potb[lane] * LOG2E);
    float p0hi = ex2f_(potb[lane + 32] * LOG2E);

    float log2A;
    if (nc == 0) {
        log2A = lg2f_(wredsum_(p0lo + p0hi));
    } else {
        float d1 = wredsum_(p0lo * g_qv[b][0][lane] + p0hi * g_qv[b][0][lane + 32]);
        log2A = lg2f_(d1) + g_qoff[b][0];
        for (int cc = 2; cc <= nc; cc++) {
            float d = wredsum_(g_rv[b][cc-2][lane]      * g_qv[b][cc-1][lane] +
                               g_rv[b][cc-2][lane + 32] * g_qv[b][cc-1][lane + 32]);
            float sig = wredsum_(g_qv[b][cc-2][lane] + g_qv[b][cc-2][lane + 32]);
            log2A += lg2f_(d) + g_roff[b][cc-2] + g_qoff[b][cc-1]
                   - lg2f_(sig) - g_qoff[b][cc-2];
        }
    }

    if (lane == 0) {
        g_partial[b] = -(g_seqs[b] - log2A * LN2) * sw[b];
        __threadfence();
    }
    __syncwarp();

    unsigned int o2 = 0;
    if (lane == 0) o2 = atomicAdd(&g_count, 1);
    o2 = __shfl_sync(0xffffffffu, o2, 0);
    if (o2 == (unsigned)B - 1) {
        if (lane == 0) { g_count = 0; __threadfence(); }
        __syncwarp();
        float tot = 0.f;
        for (int i = lane; i < B; i += 32) tot += g_partial[i];
        tot = wredsum_(tot);
        if (lane == 0) *out = tot / (float)B;
    }
}

extern "C" void kernel_launch(void* const* d_in, const int* in_sizes, int n_in,
                              void* d_out, int out_size) {
    const float* pot    = (const float*)d_in[0];
    const int*   tags   = (const int*)d_in[1];
    const int*   seqlen = (const int*)d_in[2];
    const float* K      = (const float*)d_in[3];
    const float* sw     = (const float*)d_in[4];

    int B = in_sizes[2];            // sequence_length element count
    int T = in_sizes[1] / B;        // tags is [B, T]

    crf_all_kernel<<<B * NPK, 64>>>(pot, tags, seqlen, K, sw, (float*)d_out, T, B);
}

// round 14
// speedup vs baseline: 1.2743x; 1.2743x over previous
#include <cuda_runtime.h>

#define LOG2E 1.4426950408889634f
#define LN2   0.6931471805599453f
#define CHUNK 32
#define MAXC  32         // ceil(1023/32)
#define NPK   33         // 0..15 = q-pairs (backward), 16..31 = r-pairs (forward), 32 = gathers

__device__ float g_qv[1024][MAXC][64];
__device__ float g_rv[1024][MAXC - 1][64];
__device__ float g_qoff[1024][MAXC];
__device__ float g_roff[1024][MAXC - 1];
__device__ float g_seqs[1024];
__device__ float g_partial[1024];
__device__ unsigned int g_done[1024];   // zero-init; self-resetting
__device__ unsigned int g_count = 0;

static __device__ __forceinline__ float ex2f_(float x) {
    float y; asm("ex2.approx.ftz.f32 %0, %1;" : "=f"(y) : "f"(x)); return y;
}
static __device__ __forceinline__ float lg2f_(float x) {
    float y; asm("lg2.approx.ftz.f32 %0, %1;" : "=f"(y) : "f"(x)); return y;
}
static __device__ __forceinline__ unsigned long long pack2_(float lo, float hi) {
    unsigned long long d;
    asm("mov.b64 %0, {%1, %2};" : "=l"(d) : "f"(lo), "f"(hi));
    return d;
}
static __device__ __forceinline__ unsigned long long fma2_(unsigned long long a,
                                                           unsigned long long b,
                                                           unsigned long long c) {
    unsigned long long d;
    asm("fma.rn.f32x2 %0, %1, %2, %3;" : "=l"(d) : "l"(a), "l"(b), "l"(c));
    return d;
}
static __device__ __forceinline__ unsigned long long addx2_(unsigned long long a,
                                                            unsigned long long b) {
    unsigned long long d;
    asm("add.rn.f32x2 %0, %1, %2;" : "=l"(d) : "l"(a), "l"(b));
    return d;
}
static __device__ __forceinline__ void unpack2_(unsigned long long v, float& lo, float& hi) {
    asm("mov.b64 {%0, %1}, %2;" : "=f"(lo), "=f"(hi) : "l"(v));
}
static __device__ __forceinline__ float wredsum_(float v) {
#pragma unroll
    for (int m = 16; m > 0; m >>= 1) v += __shfl_xor_sync(0xffffffffu, v, m);
    return v;
}

// Half-contraction over this warp's 32-index half of BUF for states jO and jF.
#define MACHP(BUF, SO, SF)                                                  \
    {                                                                       \
        const ulonglong2* wv_ = (const ulonglong2*)(BUF);                   \
        unsigned long long o0_=0ull, o1_=0ull, f0_=0ull, f1_=0ull;          \
        _Pragma("unroll")                                                   \
        for (int k_ = 0; k_ < 8; k_++) {                                    \
            ulonglong2 q_ = wv_[k_];                                        \
            o0_ = fma2_(q_.x, eO[2*k_],     o0_);                           \
            o1_ = fma2_(q_.y, eO[2*k_ + 1], o1_);                           \
            f0_ = fma2_(q_.x, eF[2*k_],     f0_);                           \
            f1_ = fma2_(q_.y, eF[2*k_ + 1], f1_);                           \
        }                                                                   \
        float lo_, hi_;                                                     \
        unpack2_(addx2_(o0_, o1_), lo_, hi_); SO = lo_ + hi_;               \
        unpack2_(addx2_(f0_, f1_), lo_, hi_); SF = lo_ + hi_;               \
    }

// ---------- paired bodies (two same-orientation chains, one barrier) ----------
#define BPAIR(UU, PB)                                                       \
    {                                                                       \
        float pA_, pB_;                                                     \
        if (PB) {                                                           \
            float DA_ = dshA[(PB)^1]; float lA_ = lg2f_(DA_); loffA += lA_; \
            pA_ = ex2f_(fmaf(pfA[UU], LOG2E, -lA_));                        \
            float DB_ = dshB[(PB)^1]; float lB_ = lg2f_(DB_); loffB += lB_; \
            pB_ = ex2f_(fmaf(pfB[UU], LOG2E, -lB_));                        \
        } else {                                                            \
            pA_ = ex2f_(pfA[UU] * LOG2E);                                   \
            pB_ = ex2f_(pfB[UU] * LOG2E);                                   \
        }                                                                   \
        pfA[UU] = *(const float*)(potc + offA); offA = max(offA-256, offloA);\
        pfB[UU] = *(const float*)(potc + offB); offB = max(offB-256, offloB);\
        float yA_ = xA * pA_, yB_ = xB * pB_;                               \
        wshA[jO] = yA_; wshB[jO] = yB_;                                     \
        if (jO == 0) { dshA[PB] = yA_; dshB[PB] = yB_; }                    \
        __syncwarp();                                                       \
        float sOA_, sFA_, sOB_, sFB_;                                       \
        MACHP(&wshA[h << 5], sOA_, sFA_)                                    \
        MACHP(&wshB[h << 5], sOB_, sFB_)                                    \
        ppA[PB][jF] = sFA_; ppB[PB][jF] = sFB_;                             \
        __syncthreads();                                                    \
        xA = sOA_ + ppA[PB][jO]; xB = sOB_ + ppB[PB][jO];                   \
    }

#define FPAIR(UU, PB)                                                       \
    {                                                                       \
        float pA_, pB_;                                                     \
        if (PB) {                                                           \
            float DA_ = dshA[1]; float lA_ = lg2f_(DA_); loffA += lA_;      \
            pA_ = ex2f_(fmaf(pfA[UU], LOG2E, -lA_));                        \
            float DB_ = dshB[1]; float lB_ = lg2f_(DB_); loffB += lB_;      \
            pB_ = ex2f_(fmaf(pfB[UU], LOG2E, -lB_));                        \
        } else {                                                            \
            pA_ = ex2f_(pfA[UU] * LOG2E);                                   \
            pB_ = ex2f_(pfB[UU] * LOG2E);                                   \
        }                                                                   \
        pfA[UU] = *(const float*)(potc + offA); offA = min(offA+256, offhiA);\
        pfB[UU] = *(const float*)(potc + offB); offB = min(offB+256, offhiB);\
        float sOA_, sFA_, sOB_, sFB_;                                       \
        MACHP(&wshA[h << 5], sOA_, sFA_)                                    \
        MACHP(&wshB[h << 5], sOB_, sFB_)                                    \
        ppA[PB][jF] = sFA_; ppB[PB][jF] = sFB_;                             \
        __syncthreads();                                                    \
        float vA_ = (sOA_ + ppA[PB][jO]) * pA_;                             \
        float vB_ = (sOB_ + ppB[PB][jO]) * pB_;                             \
        wshA[jO] = vA_; wshB[jO] = vB_;                                     \
        if (jO == 0) { dshA[PB] = vA_; dshB[PB] = vB_; }                    \
        __syncwarp();                                                       \
    }

// ---------- single-chain bodies (chain A only; parity-normed) ----------
#define BSING(UU, PB)                                                       \
    {                                                                       \
        float pA_;                                                          \
        if (PB) {                                                           \
            float D_ = dshA[(PB)^1]; float lD_ = lg2f_(D_); loffA += lD_;   \
            pA_ = ex2f_(fmaf(pfA[UU], LOG2E, -lD_));                        \
        } else {                                                            \
            pA_ = ex2f_(pfA[UU] * LOG2E);                                   \
        }                                                                   \
        pfA[UU] = *(const float*)(potc + offA); offA = max(offA-256, offloA);\
        float y_ = xA * pA_;                                                \
        wshA[jO] = y_;                                                      \
        if (jO == 0) dshA[PB] = y_;                                         \
        __syncwarp();                                                       \
        float sO_, sF_;                                                     \
        MACHP(&wshA[h << 5], sO_, sF_)                                      \
        ppA[PB][jF] = sF_;                                                  \
        __syncthreads();                                                    \
        xA = sO_ + ppA[PB][jO];                                             \
    }

#define FSING(UU, PB)                                                       \
    {                                                                       \
        float pA_;                                                          \
        if (PB) {                                                           \
            float D_ = dshA[1]; float lD_ = lg2f_(D_); loffA += lD_;        \
            pA_ = ex2f_(fmaf(pfA[UU], LOG2E, -lD_));                        \
        } else {                                                            \
            pA_ = ex2f_(pfA[UU] * LOG2E);                                   \
        }                                                                   \
        pfA[UU] = *(const float*)(potc + offA); offA = min(offA+256, offhiA);\
        float sO_, sF_;                                                     \
        MACHP(&wshA[h << 5], sO_, sF_)                                      \
        ppA[PB][jF] = sF_;                                                  \
        __syncthreads();                                                    \
        float v_ = (sO_ + ppA[PB][jO]) * pA_;                               \
        wshA[jO] = v_;                                                      \
        if (jO == 0) dshA[PB] = v_;                                         \
        __syncwarp();                                                       \
    }

// ---------- tail bodies (chain A, always-norm, ping-ponged slots via tp) ----------
#define BTAIL(TQ)                                                           \
    {                                                                       \
        float D_ = dshA[tp ^ 1]; float lD_ = lg2f_(D_); loffA += lD_;       \
        float p_ = ex2f_(fmaf(TQ, LOG2E, -lD_));                            \
        TQ = *(const float*)(potc + offT); offT = max(offT-256, offloA);    \
        float y_ = xA * p_;                                                 \
        wshA[jO] = y_;                                                      \
        if (jO == 0) dshA[tp] = y_;                                         \
        __syncwarp();                                                       \
        float sO_, sF_;                                                     \
        MACHP(&wshA[h << 5], sO_, sF_)                                      \
        ppA[tp][jF] = sF_;                                                  \
        __syncthreads();                                                    \
        xA = sO_ + ppA[tp][jO];                                             \
        tp ^= 1;                                                            \
    }

#define FTAIL(TQ)                                                           \
    {                                                                       \
        float D_ = dshA[tp ^ 1]; float lD_ = lg2f_(D_); loffA += lD_;       \
        float p_ = ex2f_(fmaf(TQ, LOG2E, -lD_));                            \
        TQ = *(const float*)(potc + offT); offT = min(offT+256, offhiA);    \
        float sO_, sF_;                                                     \
        MACHP(&wshA[h << 5], sO_, sF_)                                      \
        ppA[tp][jF] = sF_;                                                  \
        __syncthreads();                                                    \
        float v_ = (sO_ + ppA[tp][jO]) * p_;                                \
        wshA[jO] = v_;                                                      \
        if (jO == 0) dshA[tp] = v_;                                         \
        __syncwarp();                                                       \
        tp ^= 1;                                                            \
    }

// One CTA (64 threads, 2 warps) per (batch, task-pair).
__global__ __launch_bounds__(64, 8) void crf_all_kernel(
    const float* __restrict__ pot,     // [B, T, 64]
    const int*   __restrict__ tags,    // [B, T]
    const int*   __restrict__ seqlen,  // [B]
    const float* __restrict__ K,       // [64, 64]
    const float* __restrict__ sw,      // [B]
    float*       __restrict__ out,
    int T, int B)
{
    const int b    = blockIdx.x / NPK;
    const int k    = blockIdx.x % NPK;
    const int tid  = threadIdx.x;
    const int lane = tid & 31;
    const int h    = tid >> 5;
    const int jO   = (h << 5) + lane;
    const int jF   = ((1 - h) << 5) + lane;

    int L = seqlen[b];
    if (L > T) L = T;
    if (L < 1) L = 1;
    const int M  = L - 1;
    const int nc = (M + CHUNK - 1) / CHUNK;

    const float* potb = pot + (size_t)b * T * 64;
    const char*  potc = (const char*)potb;

    __shared__ __align__(16) float wshA[64];
    __shared__ __align__(16) float wshB[64];
    __shared__ float ppA[2][64], ppB[2][64];
    __shared__ float dshA[2], dshB[2];
    __shared__ float sred[64];

    int cnt = 1;

    if (k == NPK - 1) {
        // ================= sequence-score gathers =================
        const int* tagb = tags + (size_t)b * T;
        float acc = 0.f;
        for (int t = tid; t < T; t += 64) {
            if (t < L) {
                int tg = tagb[t];
                acc += __ldg(potb + (size_t)t * 64 + tg);
                if (t >= 1) acc += __ldg(K + tagb[t - 1] * 64 + tg);
            }
        }
        sred[tid] = acc;
        __syncthreads();
        if (h == 0) {
            float v = sred[lane] + sred[lane + 32];
            v = wredsum_(v);
            if (lane == 0) g_seqs[b] = v;
        }
    } else {
        const bool is_q = (k < 16);
        const int  kp   = is_q ? k : (k - 16);
        const int  cA   = 2 * kp + 1;
        const int  cB   = 2 * kp + 2;
        const int  cmax = is_q ? nc : (nc - 1);
        const bool validA = (cA <= cmax);
        const bool validB = (cB <= cmax);
        if (!validA) return;          // no arrival
        cnt = validB ? 2 : 1;

        const int aA = (cA - 1) * CHUNK + 1, bendA = min(cA * CHUNK, M);
        const int aB = (cB - 1) * CHUNK + 1, bendB = min(cB * CHUNK, M);
        const int nsA = bendA - aA + 1;
        const int nsB = validB ? (bendB - aB + 1) : 0;
        const int s4 = jO << 2;
        const int offloA = aA * 256 + s4, offhiA = bendA * 256 + s4;
        const int offloB = aB * 256 + s4, offhiB = bendB * 256 + s4;

        // E registers: shared by both chains (same orientation).
        unsigned long long eO[16], eF[16];
        if (is_q) {
            const float4* krO = (const float4*)(K + jO * 64 + (h << 5));
            const float4* krF = (const float4*)(K + jF * 64 + (h << 5));
#pragma unroll
            for (int m = 0; m < 8; m++) {
                float4 vO = krO[m], vF = krF[m];
                eO[2*m]   = pack2_(ex2f_(vO.x * LOG2E), ex2f_(vO.y * LOG2E));
                eO[2*m+1] = pack2_(ex2f_(vO.z * LOG2E), ex2f_(vO.w * LOG2E));
                eF[2*m]   = pack2_(ex2f_(vF.x * LOG2E), ex2f_(vF.y * LOG2E));
                eF[2*m+1] = pack2_(ex2f_(vF.z * LOG2E), ex2f_(vF.w * LOG2E));
            }
        } else {
#pragma unroll
            for (int m = 0; m < 16; m++) {
                int r0 = (h << 5) + 2 * m;
                eO[m] = pack2_(ex2f_(K[r0 * 64 + jO]       * LOG2E),
                               ex2f_(K[(r0 + 1) * 64 + jO] * LOG2E));
                eF[m] = pack2_(ex2f_(K[r0 * 64 + jF]       * LOG2E),
                               ex2f_(K[(r0 + 1) * 64 + jF] * LOG2E));
            }
        }

        float loffA = 0.f, loffB = 0.f;
        float pfA[4], pfB[4];
        int tp = 0;

        if (tid == 0) { dshA[0] = dshA[1] = 1.0f; dshB[0] = dshB[1] = 1.0f; }

        if (is_q) {
            // ======== backward chains ========
            float xA = 1.0f, xB = 1.0f;
#pragma unroll
            for (int u = 0; u < 4; u++) {
                int rA = bendA - u; if (rA < aA) rA = aA;
                pfA[u] = potb[(size_t)rA * 64 + jO];
                int rB = validB ? (bendB - u) : aA;
                if (rB < aB) rB = aB;
                pfB[u] = validB ? potb[(size_t)rB * 64 + jO] : 0.f;
            }
            int offA = (bendA - 4) * 256 + s4; if (offA < offloA) offA = offloA;
            int offB = validB ? ((bendB - 4) * 256 + s4) : offloB;
            if (offB < offloB) offB = offloB;
            __syncthreads();

            if (validB) {
                int n4 = nsB >> 2;
                for (int it = 0; it < n4; it++) {
                    BPAIR(0, 0) BPAIR(1, 1) BPAIR(2, 0) BPAIR(3, 1)
                }
                int rem = nsB & 3;
                if (rem > 0) BPAIR(0, 0)
                if (rem > 1) BPAIR(1, 1)
                if (rem > 2) BPAIR(2, 0)

                g_qv[b][cB - 1][jO] = xB;
                if (tid == 0) g_qoff[b][cB - 1] = loffB;

                // tail for A: remaining nsA - nsB bodies (A always full here)
                int rem2 = nsA - nsB;
                if (rem2 > 0) {
                    int tn = bendA - nsB;
                    int r0 = tn, r1 = tn - 1;
                    if (r1 < aA) r1 = aA;
                    float tq0 = potb[(size_t)r0 * 64 + jO];
                    float tq1 = potb[(size_t)r1 * 64 + jO];
                    int offT = (tn - 2) * 256 + s4; if (offT < offloA) offT = offloA;
                    int s = 0;
                    for (; s + 2 <= rem2; s += 2) { BTAIL(tq0) BTAIL(tq1) }
                    if (s < rem2) BTAIL(tq0)
                }
            } else {
                int n4 = nsA >> 2;
                for (int it = 0; it < n4; it++) {
                    BSING(0, 0) BSING(1, 1) BSING(2, 0) BSING(3, 1)
                }
                int rem = nsA & 3;
                if (rem > 0) BSING(0, 0)
                if (rem > 1) BSING(1, 1)
                if (rem > 2) BSING(2, 0)
            }

            g_qv[b][cA - 1][jO] = xA;
            if (tid == 0) g_qoff[b][cA - 1] = loffA;
        } else {
            // ======== forward chains ========
            wshA[jO] = 1.0f; wshB[jO] = 1.0f;
#pragma unroll
            for (int u = 0; u < 4; u++) {
                int rA = aA + u; if (rA > bendA) rA = bendA;
                pfA[u] = potb[(size_t)rA * 64 + jO];
                int rB = aB + u; if (rB > bendB) rB = bendB;
                pfB[u] = validB ? potb[(size_t)rB * 64 + jO] : 0.f;
            }
            int offA = (aA + 4) * 256 + s4; if (offA > offhiA) offA = offhiA;
            int offB = validB ? ((aB + 4) * 256 + s4) : offloB;
            if (offB > offhiB) offB = offhiB;
            __syncthreads();

            if (validB) {
                int n4 = nsB >> 2;
                for (int it = 0; it < n4; it++) {
                    FPAIR(0, 0) FPAIR(1, 1) FPAIR(2, 0) FPAIR(3, 1)
                }
                int rem = nsB & 3;
                if (rem > 0) FPAIR(0, 0)
                if (rem > 1) FPAIR(1, 1)
                if (rem > 2) FPAIR(2, 0)

                g_rv[b][cB - 1][jO] = wshB[jO];
                if (tid == 0) g_roff[b][cB - 1] = loffB;

                int rem2 = nsA - nsB;
                if (rem2 > 0) {
                    int tn = aA + nsB;
                    int r0 = tn, r1 = tn + 1;
                    if (r1 > bendA) r1 = bendA;
                    float tq0 = potb[(size_t)r0 * 64 + jO];
                    float tq1 = potb[(size_t)r1 * 64 + jO];
                    int offT = (tn + 2) * 256 + s4; if (offT > offhiA) offT = offhiA;
                    int s = 0;
                    for (; s + 2 <= rem2; s += 2) { FTAIL(tq0) FTAIL(tq1) }
                    if (s < rem2) FTAIL(tq0)
                }
            } else {
                int n4 = nsA >> 2;
                for (int it = 0; it < n4; it++) {
                    FSING(0, 0) FSING(1, 1) FSING(2, 0) FSING(3, 1)
                }
                int rem = nsA & 3;
                if (rem > 0) FSING(0, 0)
                if (rem > 1) FSING(1, 1)
                if (rem > 2) FSING(2, 0)
            }

            g_rv[b][cA - 1][jO] = wshA[jO];
            if (tid == 0) g_roff[b][cA - 1] = loffA;
        }
    }

    // ================= arrival + inline stitch (last task of batch) =================
    __threadfence();
    __syncthreads();
    if (h != 0) return;

    const unsigned int ntasks = 1u + (unsigned)nc + (unsigned)(nc > 0 ? nc - 1 : 0);
    unsigned int old = 0;
    if (lane == 0) old = atomicAdd(&g_done[b], (unsigned)cnt);
    old = __shfl_sync(0xffffffffu, old, 0);
    if (old + (unsigned)cnt != ntasks) return;

    if (lane == 0) g_done[b] = 0;    // reset for graph replay
    __threadfence();

    float p0lo = ex2f_(potb[lane] * LOG2E);
    float p0hi = ex2f_(potb[lane + 32] * LOG2E);

    float log2A;
    if (nc == 0) {
        log2A = lg2f_(wredsum_(p0lo + p0hi));
    } else {
        float d1 = wredsum_(p0lo * g_qv[b][0][lane] + p0hi * g_qv[b][0][lane + 32]);
        log2A = lg2f_(d1) + g_qoff[b][0];
        for (int cc = 2; cc <= nc; cc++) {
            float d = wredsum_(g_rv[b][cc-2][lane]      * g_qv[b][cc-1][lane] +
                               g_rv[b][cc-2][lane + 32] * g_qv[b][cc-1][lane + 32]);
            float sig = wredsum_(g_qv[b][cc-2][lane] + g_qv[b][cc-2][lane + 32]);
            log2A += lg2f_(d) + g_roff[b][cc-2] + g_qoff[b][cc-1]
                   - lg2f_(sig) - g_qoff[b][cc-2];
        }
    }

    if (lane == 0) {
        g_partial[b] = -(g_seqs[b] - log2A * LN2) * sw[b];
        __threadfence();
    }
    __syncwarp();

    unsigned int o2 = 0;
    if (lane == 0) o2 = atomicAdd(&g_count, 1);
    o2 = __shfl_sync(0xffffffffu, o2, 0);
    if (o2 == (unsigned)B - 1) {
        if (lane == 0) { g_count = 0; __threadfence(); }
        __syncwarp();
        float tot = 0.f;
        for (int i = lane; i < B; i += 32) tot += g_partial[i];
        tot = wredsum_(tot);
        if (lane == 0) *out = tot / (float)B;
    }
}

extern "C" void kernel_launch(void* const* d_in, const int* in_sizes, int n_in,
                              void* d_out, int out_size) {
    const float* pot    = (const float*)d_in[0];
    const int*   tags   = (const int*)d_in[1];
    const int*   seqlen = (const int*)d_in[2];
    const float* K      = (const float*)d_in[3];
    const float* sw     = (const float*)d_in[4];

    int B = in_sizes[2];            // sequence_length element count
    int T = in_sizes[1] / B;        // tags is [B, T]

    crf_all_kernel<<<B * NPK, 64>>>(pot, tags, seqlen, K, sw, (float*)d_out, T, B);
}